// round 16
// baseline (speedup 1.0000x reference)
#include <cuda_runtime.h>
#include <cuda_fp16.h>
#include <cstdint>

// GAT forward_user: fp16 mma.sync, persistent CTAs + dynamic queue,
// pre-converted fp16 inter (ldmatrix swizzle baked into gmem) + cp.async.
// R16: reduce fused into gat_main (per-rb done counters, last finisher
// normalizes), next-unit Q/I(0) prefetched via cp.async before the unit
// epilogue, init merged into gat_ih.

#define D_     128
#define NU_    10000
#define NI_    12000
#define BM_    64
#define NRB_   157
#define NRPAD_ (NRB_*BM_)
#define NSPL_  16
#define IPS_   768           // 64-aligned; split 15 covers 480 items
#define UNITS_ (NRB_*NSPL_)  // 2512
#define GRID_  296
#define NT_    256
#define SCALE_ 0.08838834764831843f

__device__ float    g_op[NSPL_][(size_t)NRPAD_*D_];
__device__ float    g_lp[NSPL_][NRPAD_];
__device__ uint32_t g_qf[NRB_*4096];     // Q A-frags, 16KB per row-block
__device__ uint4    g_ih[NI_*16];        // inter fp16, tile-layout swizzled
__device__ int      g_unit;
__device__ int      g_done[NRB_];

// ---- helpers ----
__device__ __forceinline__ uint32_t h2u(float a, float b){
    __half2 h = __floats2half2_rn(a, b);
    return *(uint32_t*)&h;
}
__device__ __forceinline__ void mma16(float* d, const uint32_t* a, const uint32_t* b){
    asm volatile("mma.sync.aligned.m16n8k16.row.col.f32.f16.f16.f32 "
        "{%0,%1,%2,%3}, {%4,%5,%6,%7}, {%8,%9}, {%0,%1,%2,%3};"
        : "+f"(d[0]), "+f"(d[1]), "+f"(d[2]), "+f"(d[3])
        : "r"(a[0]), "r"(a[1]), "r"(a[2]), "r"(a[3]), "r"(b[0]), "r"(b[1]));
}
__device__ __forceinline__ void ldsm4(uint32_t* r, uint32_t a){
    asm volatile("ldmatrix.sync.aligned.m8n8.x4.shared.b16 {%0,%1,%2,%3}, [%4];"
        : "=r"(r[0]), "=r"(r[1]), "=r"(r[2]), "=r"(r[3]) : "r"(a));
}
__device__ __forceinline__ void ldsm4t(uint32_t* r, uint32_t a){
    asm volatile("ldmatrix.sync.aligned.m8n8.x4.trans.shared.b16 {%0,%1,%2,%3}, [%4];"
        : "=r"(r[0]), "=r"(r[1]), "=r"(r[2]), "=r"(r[3]) : "r"(a));
}
__device__ __forceinline__ uint32_t smem_u32(const void* p){
    uint32_t a;
    asm("{ .reg .u64 t; cvta.to.shared.u64 t, %1; cvt.u32.u64 %0, t; }" : "=r"(a) : "l"(p));
    return a;
}
__device__ __forceinline__ void cpa16(uint32_t dst, const void* src){
    asm volatile("cp.async.cg.shared.global [%0], [%1], 16;" :: "r"(dst), "l"(src));
}
#define CP_COMMIT() asm volatile("cp.async.commit_group;" ::: "memory")
#define CP_WAIT0()  asm volatile("cp.async.wait_group 0;" ::: "memory")
#define BARW(id)    asm volatile("bar.sync %0, %1;" :: "r"(id), "r"(64) : "memory")

__device__ __forceinline__ int swz128(int r, int c){
    return (r<<7) | ((((c>>2) ^ (r&7)) << 2) | (c&3));
}

// smem byte offsets (gat_main)
#define B_SQ   0         // Q A-frag: [wm*8+ks][lane] uint4   16384
#define B_I0   16384     // I fp16 tile (double buffer)       16384
#define B_I1   32768     //                                   16384
#define B_SP   49152     // P A-frag                           8192
#define B_L    57344     // 128 floats                          512
#define B_U    57856     // unit broadcast (4 ints)              16
#define SMEM_B 57984

// ================= inter -> fp16 swizzled tile layout (+ init) =============
__global__ __launch_bounds__(256) void gat_ih(const float* __restrict__ inter)
{
    if (blockIdx.x == 0){
        if (threadIdx.x == 0) g_unit = 0;
        if (threadIdx.x < NRB_) g_done[threadIdx.x] = 0;
    }
    int gt = blockIdx.x*256 + threadIdx.x;       // over NI_*32
    int gm = gt >> 5, c4 = gt & 31;
    if (gm >= NI_) return;
    float4 v = *(const float4*)(inter + (size_t)gm*D_ + c4*4);
    int slot = (((c4>>1) ^ (gm&7)) << 1) | (c4 & 1);
    ((uint2*)g_ih)[gm*32 + slot] = make_uint2(h2u(v.x, v.y), h2u(v.z, v.w));
}

// ================= Q kernel: fp32-exact, store fp16 A-frags =================
__global__ __launch_bounds__(NT_, 1)
void gat_qk(const float* __restrict__ ufea, const float* __restrict__ W,
            const float* __restrict__ bias)
{
    extern __shared__ char smc[];
    float* pU = (float*)smc;                 // 32KB
    float* pW = (float*)(smc + 32768);       // 16KB
    const int tid = threadIdx.x;
    const int row0 = blockIdx.x * BM_;
    uint32_t* qw = g_qf + blockIdx.x * 4096;

    #pragma unroll
    for (int it = 0; it < 8; ++it){
        int idx = it*NT_ + tid;
        int r = idx >> 5, c4 = idx & 31;
        int gr = min(row0 + r, NU_-1);
        float4 v = *(const float4*)(ufea + (size_t)gr*D_ + c4*4);
        *(float4*)(pU + swz128(r, c4*4)) = v;
    }
    const int tx = tid & 15, ty = tid >> 4;
    #pragma unroll 1
    for (int h = 0; h < 4; ++h){
        __syncthreads();
        #pragma unroll
        for (int it = 0; it < 4; ++it){
            int idx = it*NT_ + tid;
            int lr = idx >> 5, c4 = idx & 31;
            float4 w = *(const float4*)(W + (size_t)(h*32+lr)*D_ + c4*4);
            *(float4*)(pW + swz128(lr, c4*4)) = w;
        }
        __syncthreads();
        float acc[4][2] = {};
        #pragma unroll
        for (int k4 = 0; k4 < 32; ++k4){
            float4 wv[2];
            #pragma unroll
            for (int j = 0; j < 2; ++j)
                wv[j] = *(const float4*)(pW + swz128(tx*2+j, k4*4));
            #pragma unroll
            for (int i = 0; i < 4; ++i){
                float4 uv = *(const float4*)(pU + swz128(ty*4+i, k4*4));
                #pragma unroll
                for (int j = 0; j < 2; ++j){
                    acc[i][j] += uv.x*wv[j].x; acc[i][j] += uv.y*wv[j].y;
                    acc[i][j] += uv.z*wv[j].z; acc[i][j] += uv.w*wv[j].w;
                }
            }
        }
        const int c = h*32 + tx*2;
        const int ks = c >> 4, dd = c & 15;
        const int regb = (dd < 8) ? 0 : 2;
        const int tq = (dd & 7) >> 1;
        #pragma unroll
        for (int i = 0; i < 4; ++i){
            int r = ty*4 + i;
            int wmq = r >> 4, rw = r & 15, gq = rw & 7, hi = rw >> 3;
            uint32_t pk = h2u(acc[i][0] + bias[c], acc[i][1] + bias[c+1]);
            qw[(((wmq*8 + ks)*32) + gq*4 + tq)*4 + regb + hi] = pk;
        }
    }
}

// ================= main: persistent CTAs, fused reduce =================
__global__ __launch_bounds__(NT_, 2)
void gat_main(const int* __restrict__ adj, float* __restrict__ out)
{
    extern __shared__ char smc[];
    float* sL = (float*)(smc + B_L);
    int*   sU = (int*)(smc + B_U);
    const uint32_t smb = smem_u32(smc);

    const int tid  = threadIdx.x;
    const int lane = tid & 31, warp = tid >> 5;
    const int g    = lane >> 2, tig = lane & 3;
    const int wm   = warp >> 1, wn  = warp & 1;

    const int m0 = wm*16, n0 = wn*32, nd0 = wn*64;
    const int laneM = lane & 7;
    const int jloS = ((lane>>4)&1) << 3, chS = (lane>>3)&1;
    const int jloO = ((lane>>3)&1) << 3, chO = (lane>>4)&1;
    const int jS0 = n0 + jloS + laneM,  jS1 = jS0 + 16;
    const uint32_t rbS0 = (uint32_t)(jS0*256), rbS1 = (uint32_t)(jS1*256);
    const int j7S0 = jS0 & 7, j7S1 = jS1 & 7;
    const int cpj = tid >> 4, cpc = (tid & 15) << 4;

    // ---- grab first unit, issue its Q + I(0) ----
    if (tid == 0) sU[0] = atomicAdd(&g_unit, 1);
    __syncthreads();
    {
        const int u0 = sU[0];
        if (u0 < UNITS_){
            const int rb0 = u0 % NRB_, it0 = (u0 / NRB_) * IPS_;
            cpa16(smb + B_SQ + (uint32_t)(tid*16),
                  (const char*)g_qf + (size_t)rb0*16384 + tid*16);
            cpa16(smb + B_SQ + (uint32_t)(4096 + tid*16),
                  (const char*)g_qf + (size_t)rb0*16384 + 4096 + tid*16);
            cpa16(smb + B_SQ + (uint32_t)(8192 + tid*16),
                  (const char*)g_qf + (size_t)rb0*16384 + 8192 + tid*16);
            cpa16(smb + B_SQ + (uint32_t)(12288 + tid*16),
                  (const char*)g_qf + (size_t)rb0*16384 + 12288 + tid*16);
            #pragma unroll
            for (int it = 0; it < 4; ++it){
                int j = it*16 + cpj;
                int gm = min(it0 + j, NI_-1);
                cpa16(smb + B_I0 + (uint32_t)(j*256 + cpc),
                      (const char*)g_ih + (size_t)gm*256 + cpc);
            }
            CP_COMMIT();
        }
    }

    for (;;){
        const int u = sU[0];
        if (u >= UNITS_) break;
        const int spl = u / NRB_, rb = u - spl*NRB_;
        const int row0 = rb*BM_, item0 = spl*IPS_;
        const int valid = min(IPS_, NI_ - item0);   // 768, or 480 for spl=15
        const int nt = (valid + 63) >> 6;           // 12 or 8 (always even)

        float oacc[8][4];
        #pragma unroll
        for (int i = 0; i < 8; ++i)
            #pragma unroll
            for (int j = 0; j < 4; ++j) oacc[i][j] = 0.f;
        float lacc0 = 0.f, lacc1 = 0.f;

        const int gr0 = min(row0 + m0 + g,     NU_-1);
        const int gr1 = min(row0 + m0 + 8 + g, NU_-1);
        const size_t arow0 = (size_t)gr0*NI_ + item0;
        const size_t arow1 = (size_t)gr1*NI_ + item0;

        #pragma unroll 1
        for (int t = 0; t < nt; ++t){
            const uint32_t ibase = smb + ((t & 1) ? B_I1 : B_I0);
            const uint32_t nbase = smb + ((t & 1) ? B_I0 : B_I1);

            CP_WAIT0();                      // I(t) (+Q at t=0) landed
            __syncthreads();                 // publish; O(t-1) readers done

            // ---- issue I(t+1) into freed buffer ----
            if (t+1 < nt){
                #pragma unroll
                for (int it = 0; it < 4; ++it){
                    int j = it*16 + cpj;
                    int gm = min(item0 + (t+1)*64 + j, NI_-1);
                    cpa16(nbase + (uint32_t)(j*256 + cpc),
                          (const char*)g_ih + (size_t)gm*256 + cpc);
                }
                CP_COMMIT();
            }

            // ---- adj(t) prefetch (direct LDG int2) ----
            int2 a0[4], a1[4];
            #pragma unroll
            for (int nf = 0; nf < 4; ++nf){
                const int lc = t*64 + n0 + nf*8 + 2*tig;
                if (lc < valid){
                    a0[nf] = *(const int2*)(adj + arow0 + lc);
                    a1[nf] = *(const int2*)(adj + arow1 + lc);
                } else {
                    a0[nf] = make_int2(0,0); a1[nf] = make_int2(0,0);
                }
            }

            // ---- S = Q . I^T ----
            float sacc[4][4];
            #pragma unroll
            for (int nf = 0; nf < 4; ++nf)
                #pragma unroll
                for (int j = 0; j < 4; ++j) sacc[nf][j] = 0.f;
            #pragma unroll
            for (int ks = 0; ks < 8; ++ks){
                uint4 a4 = *(const uint4*)(smc + B_SQ + (((wm*8+ks)*32 + lane)<<4));
                const uint32_t A[4] = { a4.x, a4.y, a4.z, a4.w };
                uint32_t r[4];
                ldsm4(r, ibase + rbS0 + (uint32_t)((((2*ks + chS) ^ j7S0))<<4));
                mma16(sacc[0], A, r);
                mma16(sacc[1], A, r+2);
                ldsm4(r, ibase + rbS1 + (uint32_t)((((2*ks + chS) ^ j7S1))<<4));
                mma16(sacc[2], A, r);
                mma16(sacc[3], A, r+2);
            }

            // ---- epilogue: scale, leaky2, mask, exp; P -> fp16 A-frags ----
            #pragma unroll
            for (int nf = 0; nf < 4; ++nf){
                float v00 = sacc[nf][0]*SCALE_; v00 = fminf(v00, 2.f*v00);
                float v01 = sacc[nf][1]*SCALE_; v01 = fminf(v01, 2.f*v01);
                float v10 = sacc[nf][2]*SCALE_; v10 = fminf(v10, 2.f*v10);
                float v11 = sacc[nf][3]*SCALE_; v11 = fminf(v11, 2.f*v11);
                float p00 = (a0[nf].x > 0) ? __expf(v00) : 0.f;
                float p01 = (a0[nf].y > 0) ? __expf(v01) : 0.f;
                float p10 = (a1[nf].x > 0) ? __expf(v10) : 0.f;
                float p11 = (a1[nf].y > 0) ? __expf(v11) : 0.f;
                lacc0 += p00 + p01;
                lacc1 += p10 + p11;
                sacc[nf][0] = p00; sacc[nf][1] = p01;
                sacc[nf][2] = p10; sacc[nf][3] = p11;
            }
            #pragma unroll
            for (int kl = 0; kl < 2; ++kl){
                uint4 pk;
                pk.x = h2u(sacc[2*kl][0],   sacc[2*kl][1]);
                pk.y = h2u(sacc[2*kl][2],   sacc[2*kl][3]);
                pk.z = h2u(sacc[2*kl+1][0], sacc[2*kl+1][1]);
                pk.w = h2u(sacc[2*kl+1][2], sacc[2*kl+1][3]);
                *(uint4*)(smc + B_SP + (((wm*4 + wn*2 + kl)*32 + lane)<<4)) = pk;
            }
            BARW(1 + wm);                    // P visible within wm-pair

            // ---- O += P . I ----
            #pragma unroll
            for (int kso = 0; kso < 4; ++kso){
                uint4 a4 = *(const uint4*)(smc + B_SP + (((wm*4+kso)*32 + lane)<<4));
                const uint32_t A[4] = { a4.x, a4.y, a4.z, a4.w };
                const int j = kso*16 + jloO + laneM;
                const uint32_t rbb = ibase + (uint32_t)(j*256);
                const int j7 = j & 7;
                #pragma unroll
                for (int nh = 0; nh < 4; ++nh){
                    uint32_t r[4];
                    ldsm4t(r, rbb + (uint32_t)(((((nd0>>3) + nh*2 + chO) ^ j7))<<4));
                    mma16(oacc[nh*2],   A, r);
                    mma16(oacc[nh*2+1], A, r+2);
                }
            }
        }

        // ---- l reduction ----
        lacc0 += __shfl_xor_sync(0xffffffffu, lacc0, 1);
        lacc0 += __shfl_xor_sync(0xffffffffu, lacc0, 2);
        lacc1 += __shfl_xor_sync(0xffffffffu, lacc1, 1);
        lacc1 += __shfl_xor_sync(0xffffffffu, lacc1, 2);
        __syncthreads();                     // all O-mma / Q reads done
        if (tid == 0) sU[0] = atomicAdd(&g_unit, 1);
        if (tig == 0){
            sL[wn*64 + m0 + g]     = lacc0;
            sL[wn*64 + m0 + 8 + g] = lacc1;
        }
        __syncthreads();                     // sL + sU[0] visible

        // ---- prefetch next unit's Q + I(0) (B_SQ/B_I0 now free) ----
        {
            const int un = sU[0];
            if (un < UNITS_){
                const int rbn = un % NRB_, itn = (un / NRB_) * IPS_;
                cpa16(smb + B_SQ + (uint32_t)(tid*16),
                      (const char*)g_qf + (size_t)rbn*16384 + tid*16);
                cpa16(smb + B_SQ + (uint32_t)(4096 + tid*16),
                      (const char*)g_qf + (size_t)rbn*16384 + 4096 + tid*16);
                cpa16(smb + B_SQ + (uint32_t)(8192 + tid*16),
                      (const char*)g_qf + (size_t)rbn*16384 + 8192 + tid*16);
                cpa16(smb + B_SQ + (uint32_t)(12288 + tid*16),
                      (const char*)g_qf + (size_t)rbn*16384 + 12288 + tid*16);
                #pragma unroll
                for (int it = 0; it < 4; ++it){
                    int j = it*16 + cpj;
                    int gm = min(itn + j, NI_-1);
                    cpa16(smb + B_I0 + (uint32_t)(j*256 + cpc),
                          (const char*)g_ih + (size_t)gm*256 + cpc);
                }
                CP_COMMIT();
            }
        }

        if (tid < BM_) g_lp[spl][row0 + tid] = sL[tid] + sL[64 + tid];

        // ---- write unnormalized partial O ----
        {
            const int r0g = row0 + m0 + g, r1g = row0 + m0 + 8 + g;
            #pragma unroll
            for (int nf = 0; nf < 8; ++nf){
                const int dd = nd0 + nf*8 + 2*tig;
                if (r0g < NU_)
                    *(float2*)(&g_op[spl][(size_t)r0g*D_ + dd]) =
                        make_float2(oacc[nf][0], oacc[nf][1]);
                if (r1g < NU_)
                    *(float2*)(&g_op[spl][(size_t)r1g*D_ + dd]) =
                        make_float2(oacc[nf][2], oacc[nf][3]);
            }
        }

        // ---- completion count; last finisher reduces this row-block ----
        __threadfence();
        if (tid == 0) sU[1] = atomicAdd(&g_done[rb], 1);
        __syncthreads();
        if (sU[1] == NSPL_ - 1){
            __threadfence();
            if (tid < BM_){
                float l = 0.f;
                #pragma unroll
                for (int s = 0; s < NSPL_; ++s) l += __ldcg(&g_lp[s][row0 + tid]);
                sL[tid] = 1.0f / l;
            }
            __syncthreads();
            #pragma unroll
            for (int k = 0; k < 8; ++k){
                int idx = k*256 + tid;
                int r = idx >> 5, c4 = idx & 31;
                int row = row0 + r;
                if (row < NU_){
                    float4 acc = make_float4(0.f, 0.f, 0.f, 0.f);
                    #pragma unroll
                    for (int s = 0; s < NSPL_; ++s){
                        float4 a = __ldcg((const float4*)(&g_op[s][(size_t)row*D_ + c4*4]));
                        acc.x += a.x; acc.y += a.y; acc.z += a.z; acc.w += a.w;
                    }
                    float inv = sL[r];
                    *(float4*)(out + (size_t)row*D_ + c4*4) =
                        make_float4(acc.x*inv, acc.y*inv, acc.z*inv, acc.w*inv);
                }
            }
            __syncthreads();                 // sL free before next unit
        }
    }
}

extern "C" void kernel_launch(void* const* d_in, const int* in_sizes, int n_in,
                              void* d_out, int out_size)
{
    const float* ufea  = (const float*)d_in[0];
    const float* inter = (const float*)d_in[1];
    const int*   adj   = (const int*)  d_in[2];
    const float* W     = (const float*)d_in[3];
    const float* bias  = (const float*)d_in[4];
    for (int i = 0; i < n_in; ++i) {
        int s = in_sizes[i];
        if      (s == NU_*D_)  ufea  = (const float*)d_in[i];
        else if (s == NI_*D_)  inter = (const float*)d_in[i];
        else if (s == NU_*NI_) adj   = (const int*)d_in[i];
        else if (s == D_*D_)   W     = (const float*)d_in[i];
        else if (s == D_)      bias  = (const float*)d_in[i];
    }

    cudaFuncSetAttribute(gat_qk,   cudaFuncAttributeMaxDynamicSharedMemorySize, 49152);
    cudaFuncSetAttribute(gat_main, cudaFuncAttributeMaxDynamicSharedMemorySize, SMEM_B);

    gat_ih<<<(NI_*32 + 255)/256, 256>>>(inter);
    gat_qk<<<NRB_, NT_, 49152>>>(ufea, W, bias);
    gat_main<<<GRID_, NT_, SMEM_B>>>(adj, (float*)d_out);
}

// round 17
// speedup vs baseline: 1.0122x; 1.0122x over previous
#include <cuda_runtime.h>
#include <cuda_fp16.h>
#include <cstdint>

// GAT forward_user: fp16 mma.sync, persistent CTAs + dynamic queue,
// pre-converted fp16 inter (ldmatrix swizzle baked into gmem) + cp.async.
// R17: O-gemm warp retile 16x64 -> 32x32 (warp grid re-mapped between S and
// O phases; P is in smem so any warp can read any P). B-frag ldsm halves,
// A(P) LDS doubles: net -16 wavefronts/warp/tile, same registers, identical
// per-output accumulation order. Named barrier replaced by one syncthreads.

#define D_     128
#define NU_    10000
#define NI_    12000
#define BM_    64
#define NRB_   157
#define NRPAD_ (NRB_*BM_)
#define NSPL_  16
#define IPS_   768           // 64-aligned; split 15 covers 480 items
#define UNITS_ (NRB_*NSPL_)  // 2512
#define GRID_  296
#define NT_    256
#define SCALE_ 0.08838834764831843f

__device__ float    g_op[NSPL_][(size_t)NRPAD_*D_];
__device__ float    g_lp[NSPL_][NRPAD_];
__device__ uint32_t g_qf[NRB_*4096];     // Q A-frags, 16KB per row-block
__device__ uint4    g_ih[NI_*16];        // inter fp16, tile-layout swizzled
__device__ int      g_unit;
__device__ int      g_done[NRB_];

// ---- helpers ----
__device__ __forceinline__ uint32_t h2u(float a, float b){
    __half2 h = __floats2half2_rn(a, b);
    return *(uint32_t*)&h;
}
__device__ __forceinline__ void mma16(float* d, const uint32_t* a, const uint32_t* b){
    asm volatile("mma.sync.aligned.m16n8k16.row.col.f32.f16.f16.f32 "
        "{%0,%1,%2,%3}, {%4,%5,%6,%7}, {%8,%9}, {%0,%1,%2,%3};"
        : "+f"(d[0]), "+f"(d[1]), "+f"(d[2]), "+f"(d[3])
        : "r"(a[0]), "r"(a[1]), "r"(a[2]), "r"(a[3]), "r"(b[0]), "r"(b[1]));
}
__device__ __forceinline__ void ldsm4(uint32_t* r, uint32_t a){
    asm volatile("ldmatrix.sync.aligned.m8n8.x4.shared.b16 {%0,%1,%2,%3}, [%4];"
        : "=r"(r[0]), "=r"(r[1]), "=r"(r[2]), "=r"(r[3]) : "r"(a));
}
__device__ __forceinline__ void ldsm4t(uint32_t* r, uint32_t a){
    asm volatile("ldmatrix.sync.aligned.m8n8.x4.trans.shared.b16 {%0,%1,%2,%3}, [%4];"
        : "=r"(r[0]), "=r"(r[1]), "=r"(r[2]), "=r"(r[3]) : "r"(a));
}
__device__ __forceinline__ uint32_t smem_u32(const void* p){
    uint32_t a;
    asm("{ .reg .u64 t; cvta.to.shared.u64 t, %1; cvt.u32.u64 %0, t; }" : "=r"(a) : "l"(p));
    return a;
}
__device__ __forceinline__ void cpa16(uint32_t dst, const void* src){
    asm volatile("cp.async.cg.shared.global [%0], [%1], 16;" :: "r"(dst), "l"(src));
}
#define CP_COMMIT() asm volatile("cp.async.commit_group;" ::: "memory")
#define CP_WAIT0()  asm volatile("cp.async.wait_group 0;" ::: "memory")

__device__ __forceinline__ int swz128(int r, int c){
    return (r<<7) | ((((c>>2) ^ (r&7)) << 2) | (c&3));
}

// smem byte offsets (gat_main)
#define B_SQ   0         // Q A-frag: [wm*8+ks][lane] uint4   16384
#define B_I0   16384     // I fp16 tile (double buffer)       16384
#define B_I1   32768     //                                   16384
#define B_SP   49152     // P A-frag: [rg8][kso4... ][lane]     8192
#define B_L    57344     // 128 floats                          512
#define B_U    57856     // unit broadcast (4 ints)              16
#define SMEM_B 57984

// ================= inter -> fp16 swizzled tile layout (+ init) =============
__global__ __launch_bounds__(256) void gat_ih(const float* __restrict__ inter)
{
    if (blockIdx.x == 0){
        if (threadIdx.x == 0) g_unit = 0;
        if (threadIdx.x < NRB_) g_done[threadIdx.x] = 0;
    }
    int gt = blockIdx.x*256 + threadIdx.x;       // over NI_*32
    int gm = gt >> 5, c4 = gt & 31;
    if (gm >= NI_) return;
    float4 v = *(const float4*)(inter + (size_t)gm*D_ + c4*4);
    int slot = (((c4>>1) ^ (gm&7)) << 1) | (c4 & 1);
    ((uint2*)g_ih)[gm*32 + slot] = make_uint2(h2u(v.x, v.y), h2u(v.z, v.w));
}

// ================= Q kernel: fp32-exact, store fp16 A-frags =================
__global__ __launch_bounds__(NT_, 1)
void gat_qk(const float* __restrict__ ufea, const float* __restrict__ W,
            const float* __restrict__ bias)
{
    extern __shared__ char smc[];
    float* pU = (float*)smc;                 // 32KB
    float* pW = (float*)(smc + 32768);       // 16KB
    const int tid = threadIdx.x;
    const int row0 = blockIdx.x * BM_;
    uint32_t* qw = g_qf + blockIdx.x * 4096;

    #pragma unroll
    for (int it = 0; it < 8; ++it){
        int idx = it*NT_ + tid;
        int r = idx >> 5, c4 = idx & 31;
        int gr = min(row0 + r, NU_-1);
        float4 v = *(const float4*)(ufea + (size_t)gr*D_ + c4*4);
        *(float4*)(pU + swz128(r, c4*4)) = v;
    }
    const int tx = tid & 15, ty = tid >> 4;
    #pragma unroll 1
    for (int h = 0; h < 4; ++h){
        __syncthreads();
        #pragma unroll
        for (int it = 0; it < 4; ++it){
            int idx = it*NT_ + tid;
            int lr = idx >> 5, c4 = idx & 31;
            float4 w = *(const float4*)(W + (size_t)(h*32+lr)*D_ + c4*4);
            *(float4*)(pW + swz128(lr, c4*4)) = w;
        }
        __syncthreads();
        float acc[4][2] = {};
        #pragma unroll
        for (int k4 = 0; k4 < 32; ++k4){
            float4 wv[2];
            #pragma unroll
            for (int j = 0; j < 2; ++j)
                wv[j] = *(const float4*)(pW + swz128(tx*2+j, k4*4));
            #pragma unroll
            for (int i = 0; i < 4; ++i){
                float4 uv = *(const float4*)(pU + swz128(ty*4+i, k4*4));
                #pragma unroll
                for (int j = 0; j < 2; ++j){
                    acc[i][j] += uv.x*wv[j].x; acc[i][j] += uv.y*wv[j].y;
                    acc[i][j] += uv.z*wv[j].z; acc[i][j] += uv.w*wv[j].w;
                }
            }
        }
        const int c = h*32 + tx*2;
        const int ks = c >> 4, dd = c & 15;
        const int regb = (dd < 8) ? 0 : 2;
        const int tq = (dd & 7) >> 1;
        #pragma unroll
        for (int i = 0; i < 4; ++i){
            int r = ty*4 + i;
            int wmq = r >> 4, rw = r & 15, gq = rw & 7, hi = rw >> 3;
            uint32_t pk = h2u(acc[i][0] + bias[c], acc[i][1] + bias[c+1]);
            qw[(((wmq*8 + ks)*32) + gq*4 + tq)*4 + regb + hi] = pk;
        }
    }
}

// ================= main: persistent CTAs, fused reduce =================
__global__ __launch_bounds__(NT_, 2)
void gat_main(const int* __restrict__ adj, float* __restrict__ out)
{
    extern __shared__ char smc[];
    float* sL = (float*)(smc + B_L);
    int*   sU = (int*)(smc + B_U);
    const uint32_t smb = smem_u32(smc);

    const int tid  = threadIdx.x;
    const int lane = tid & 31, warp = tid >> 5;
    const int g    = lane >> 2, tig = lane & 3;
    const int wm   = warp >> 1, wn  = warp & 1;     // S-phase warp grid 4x2
    const int wm2  = warp >> 2, wn2 = warp & 3;     // O-phase warp grid 2x4

    const int m0 = wm*16, n0 = wn*32;
    const int laneM = lane & 7;
    const int jloS = ((lane>>4)&1) << 3, chS = (lane>>3)&1;
    const int jloO = ((lane>>3)&1) << 3, chO = (lane>>4)&1;
    const int jS0 = n0 + jloS + laneM,  jS1 = jS0 + 16;
    const uint32_t rbS0 = (uint32_t)(jS0*256), rbS1 = (uint32_t)(jS1*256);
    const int j7S0 = jS0 & 7, j7S1 = jS1 & 7;
    const int cpj = tid >> 4, cpc = (tid & 15) << 4;

    // ---- grab first unit, issue its Q + I(0) ----
    if (tid == 0) sU[0] = atomicAdd(&g_unit, 1);
    __syncthreads();
    {
        const int u0 = sU[0];
        if (u0 < UNITS_){
            const int rb0 = u0 % NRB_, it0 = (u0 / NRB_) * IPS_;
            #pragma unroll
            for (int k = 0; k < 4; ++k)
                cpa16(smb + B_SQ + (uint32_t)(k*4096 + tid*16),
                      (const char*)g_qf + (size_t)rb0*16384 + k*4096 + tid*16);
            #pragma unroll
            for (int it = 0; it < 4; ++it){
                int j = it*16 + cpj;
                int gm = min(it0 + j, NI_-1);
                cpa16(smb + B_I0 + (uint32_t)(j*256 + cpc),
                      (const char*)g_ih + (size_t)gm*256 + cpc);
            }
            CP_COMMIT();
        }
    }

    for (;;){
        const int u = sU[0];
        if (u >= UNITS_) break;
        const int spl = u / NRB_, rb = u - spl*NRB_;
        const int row0 = rb*BM_, item0 = spl*IPS_;
        const int valid = min(IPS_, NI_ - item0);   // 768, or 480 for spl=15
        const int nt = (valid + 63) >> 6;           // 12 or 8 (always even)

        float oacc[2][4][4];                        // [rg][dimfrag][4]
        #pragma unroll
        for (int a = 0; a < 2; ++a)
            #pragma unroll
            for (int i = 0; i < 4; ++i)
                #pragma unroll
                for (int j = 0; j < 4; ++j) oacc[a][i][j] = 0.f;
        float lacc0 = 0.f, lacc1 = 0.f;

        const int gr0 = min(row0 + m0 + g,     NU_-1);
        const int gr1 = min(row0 + m0 + 8 + g, NU_-1);
        const size_t arow0 = (size_t)gr0*NI_ + item0;
        const size_t arow1 = (size_t)gr1*NI_ + item0;

        #pragma unroll 1
        for (int t = 0; t < nt; ++t){
            const uint32_t ibase = smb + ((t & 1) ? B_I1 : B_I0);
            const uint32_t nbase = smb + ((t & 1) ? B_I0 : B_I1);

            CP_WAIT0();                      // I(t) (+Q at t=0) landed
            __syncthreads();                 // publish; O(t-1) readers done

            // ---- issue I(t+1) into freed buffer ----
            if (t+1 < nt){
                #pragma unroll
                for (int it = 0; it < 4; ++it){
                    int j = it*16 + cpj;
                    int gm = min(item0 + (t+1)*64 + j, NI_-1);
                    cpa16(nbase + (uint32_t)(j*256 + cpc),
                          (const char*)g_ih + (size_t)gm*256 + cpc);
                }
                CP_COMMIT();
            }

            // ---- adj(t) prefetch (direct LDG int2) ----
            int2 a0[4], a1[4];
            #pragma unroll
            for (int nf = 0; nf < 4; ++nf){
                const int lc = t*64 + n0 + nf*8 + 2*tig;
                if (lc < valid){
                    a0[nf] = *(const int2*)(adj + arow0 + lc);
                    a1[nf] = *(const int2*)(adj + arow1 + lc);
                } else {
                    a0[nf] = make_int2(0,0); a1[nf] = make_int2(0,0);
                }
            }

            // ---- S = Q . I^T  (warp grid 4x2: 16 rows x 32 items) ----
            float sacc[4][4];
            #pragma unroll
            for (int nf = 0; nf < 4; ++nf)
                #pragma unroll
                for (int j = 0; j < 4; ++j) sacc[nf][j] = 0.f;
            #pragma unroll
            for (int ks = 0; ks < 8; ++ks){
                uint4 a4 = *(const uint4*)(smc + B_SQ + (((wm*8+ks)*32 + lane)<<4));
                const uint32_t A[4] = { a4.x, a4.y, a4.z, a4.w };
                uint32_t r[4];
                ldsm4(r, ibase + rbS0 + (uint32_t)((((2*ks + chS) ^ j7S0))<<4));
                mma16(sacc[0], A, r);
                mma16(sacc[1], A, r+2);
                ldsm4(r, ibase + rbS1 + (uint32_t)((((2*ks + chS) ^ j7S1))<<4));
                mma16(sacc[2], A, r);
                mma16(sacc[3], A, r+2);
            }

            // ---- epilogue: scale, leaky2, mask, exp; P -> fp16 A-frags ----
            #pragma unroll
            for (int nf = 0; nf < 4; ++nf){
                float v00 = sacc[nf][0]*SCALE_; v00 = fminf(v00, 2.f*v00);
                float v01 = sacc[nf][1]*SCALE_; v01 = fminf(v01, 2.f*v01);
                float v10 = sacc[nf][2]*SCALE_; v10 = fminf(v10, 2.f*v10);
                float v11 = sacc[nf][3]*SCALE_; v11 = fminf(v11, 2.f*v11);
                float p00 = (a0[nf].x > 0) ? __expf(v00) : 0.f;
                float p01 = (a0[nf].y > 0) ? __expf(v01) : 0.f;
                float p10 = (a1[nf].x > 0) ? __expf(v10) : 0.f;
                float p11 = (a1[nf].y > 0) ? __expf(v11) : 0.f;
                lacc0 += p00 + p01;
                lacc1 += p10 + p11;
                sacc[nf][0] = p00; sacc[nf][1] = p01;
                sacc[nf][2] = p10; sacc[nf][3] = p11;
            }
            #pragma unroll
            for (int kl = 0; kl < 2; ++kl){
                uint4 pk;
                pk.x = h2u(sacc[2*kl][0],   sacc[2*kl][1]);
                pk.y = h2u(sacc[2*kl][2],   sacc[2*kl][3]);
                pk.z = h2u(sacc[2*kl+1][0], sacc[2*kl+1][1]);
                pk.w = h2u(sacc[2*kl+1][2], sacc[2*kl+1][3]);
                // index encodes (rows wm*16, item-chunk wn*2+kl of 4)
                *(uint4*)(smc + B_SP + (((wm*4 + wn*2 + kl)*32 + lane)<<4)) = pk;
            }
            __syncthreads();                 // P visible CTA-wide

            // ---- O += P . I  (warp grid 2x4: 32 rows x 32 dims) ----
            #pragma unroll
            for (int kso = 0; kso < 4; ++kso){
                uint4 af[2];
                #pragma unroll
                for (int rg = 0; rg < 2; ++rg)
                    af[rg] = *(const uint4*)(smc + B_SP +
                              ((((wm2*2 + rg)*4 + kso)*32 + lane)<<4));
                const int j = kso*16 + jloO + laneM;
                const uint32_t rbb = ibase + (uint32_t)(j*256);
                const int j7 = j & 7;
                #pragma unroll
                for (int sub = 0; sub < 2; ++sub){
                    uint32_t r[4];
                    ldsm4t(r, rbb + (uint32_t)((((wn2*4 + sub*2 + chO) ^ j7))<<4));
                    #pragma unroll
                    for (int rg = 0; rg < 2; ++rg){
                        const uint32_t A[4] = { af[rg].x, af[rg].y, af[rg].z, af[rg].w };
                        mma16(oacc[rg][sub*2],   A, r);
                        mma16(oacc[rg][sub*2+1], A, r+2);
                    }
                }
            }
        }

        // ---- l reduction ----
        lacc0 += __shfl_xor_sync(0xffffffffu, lacc0, 1);
        lacc0 += __shfl_xor_sync(0xffffffffu, lacc0, 2);
        lacc1 += __shfl_xor_sync(0xffffffffu, lacc1, 1);
        lacc1 += __shfl_xor_sync(0xffffffffu, lacc1, 2);
        __syncthreads();                     // all O-mma / Q reads done
        if (tid == 0) sU[0] = atomicAdd(&g_unit, 1);
        if (tig == 0){
            sL[wn*64 + m0 + g]     = lacc0;
            sL[wn*64 + m0 + 8 + g] = lacc1;
        }
        __syncthreads();                     // sL + sU[0] visible

        // ---- prefetch next unit's Q + I(0) (B_SQ/B_I0 now free) ----
        {
            const int un = sU[0];
            if (un < UNITS_){
                const int rbn = un % NRB_, itn = (un / NRB_) * IPS_;
                #pragma unroll
                for (int k = 0; k < 4; ++k)
                    cpa16(smb + B_SQ + (uint32_t)(k*4096 + tid*16),
                          (const char*)g_qf + (size_t)rbn*16384 + k*4096 + tid*16);
                #pragma unroll
                for (int it = 0; it < 4; ++it){
                    int j = it*16 + cpj;
                    int gm = min(itn + j, NI_-1);
                    cpa16(smb + B_I0 + (uint32_t)(j*256 + cpc),
                          (const char*)g_ih + (size_t)gm*256 + cpc);
                }
                CP_COMMIT();
            }
        }

        if (tid < BM_) g_lp[spl][row0 + tid] = sL[tid] + sL[64 + tid];

        // ---- write unnormalized partial O (O-phase warp grid) ----
        {
            #pragma unroll
            for (int rg = 0; rg < 2; ++rg){
                const int r0g = row0 + wm2*32 + rg*16 + g;
                const int r1g = r0g + 8;
                #pragma unroll
                for (int nf = 0; nf < 4; ++nf){
                    const int dd = wn2*32 + nf*8 + 2*tig;
                    if (r0g < NU_)
                        *(float2*)(&g_op[spl][(size_t)r0g*D_ + dd]) =
                            make_float2(oacc[rg][nf][0], oacc[rg][nf][1]);
                    if (r1g < NU_)
                        *(float2*)(&g_op[spl][(size_t)r1g*D_ + dd]) =
                            make_float2(oacc[rg][nf][2], oacc[rg][nf][3]);
                }
            }
        }

        // ---- completion count; last finisher reduces this row-block ----
        __threadfence();
        if (tid == 0) sU[1] = atomicAdd(&g_done[rb], 1);
        __syncthreads();
        if (sU[1] == NSPL_ - 1){
            __threadfence();
            if (tid < BM_){
                float l = 0.f;
                #pragma unroll
                for (int s = 0; s < NSPL_; ++s) l += __ldcg(&g_lp[s][row0 + tid]);
                sL[tid] = 1.0f / l;
            }
            __syncthreads();
            #pragma unroll
            for (int k = 0; k < 8; ++k){
                int idx = k*256 + tid;
                int r = idx >> 5, c4 = idx & 31;
                int row = row0 + r;
                if (row < NU_){
                    float4 acc = make_float4(0.f, 0.f, 0.f, 0.f);
                    #pragma unroll
                    for (int s = 0; s < NSPL_; ++s){
                        float4 a = __ldcg((const float4*)(&g_op[s][(size_t)row*D_ + c4*4]));
                        acc.x += a.x; acc.y += a.y; acc.z += a.z; acc.w += a.w;
                    }
                    float inv = sL[r];
                    *(float4*)(out + (size_t)row*D_ + c4*4) =
                        make_float4(acc.x*inv, acc.y*inv, acc.z*inv, acc.w*inv);
                }
            }
            __syncthreads();                 // sL free before next unit
        }
    }
}

extern "C" void kernel_launch(void* const* d_in, const int* in_sizes, int n_in,
                              void* d_out, int out_size)
{
    const float* ufea  = (const float*)d_in[0];
    const float* inter = (const float*)d_in[1];
    const int*   adj   = (const int*)  d_in[2];
    const float* W     = (const float*)d_in[3];
    const float* bias  = (const float*)d_in[4];
    for (int i = 0; i < n_in; ++i) {
        int s = in_sizes[i];
        if      (s == NU_*D_)  ufea  = (const float*)d_in[i];
        else if (s == NI_*D_)  inter = (const float*)d_in[i];
        else if (s == NU_*NI_) adj   = (const int*)d_in[i];
        else if (s == D_*D_)   W     = (const float*)d_in[i];
        else if (s == D_)      bias  = (const float*)d_in[i];
    }

    cudaFuncSetAttribute(gat_qk,   cudaFuncAttributeMaxDynamicSharedMemorySize, 49152);
    cudaFuncSetAttribute(gat_main, cudaFuncAttributeMaxDynamicSharedMemorySize, SMEM_B);

    gat_ih<<<(NI_*32 + 255)/256, 256>>>(inter);
    gat_qk<<<NRB_, NT_, 49152>>>(ufea, W, bias);
    gat_main<<<GRID_, NT_, SMEM_B>>>(adj, (float*)d_out);
}